// round 3
// baseline (speedup 1.0000x reference)
#include <cuda_runtime.h>

#define NO   20000
#define KC   11
#define DIM  256
#define OUTF 128
#define KSEL 10

// ---- scratch (no allocations allowed) ----
__device__ float        g_wa2[2 * DIM];   // W @ A[OUTF:, 0], length 512
__device__ double       g_sumA;           // sum over selected dmc rows
__device__ double       g_sumB;           // sum over dropped dmc rows
__device__ unsigned int g_done;           // completed-CTA counter

// Kernel 1: wa2[d] = sum_f W[d,f] * A[OUTF+f]; one warp per d (512 warps).
// Also zeroes the accumulators + counter (graph-replay safe).
__global__ void __launch_bounds__(256) prep_kernel(const float* __restrict__ W,
                                                   const float* __restrict__ A) {
    const int warp = (blockIdx.x * blockDim.x + threadIdx.x) >> 5;  // 0..511 = d
    const int lane = threadIdx.x & 31;

    const float* wrow = W + (size_t)warp * OUTF;
    const float* a2   = A + OUTF;
    float acc = wrow[lane]      * a2[lane]
              + wrow[lane + 32] * a2[lane + 32]
              + wrow[lane + 64] * a2[lane + 64]
              + wrow[lane + 96] * a2[lane + 96];
#pragma unroll
    for (int off = 16; off; off >>= 1)
        acc += __shfl_down_sync(0xffffffffu, acc, off);
    if (lane == 0) g_wa2[warp] = acc;

    if (blockIdx.x == 0 && threadIdx.x == 0) {
        g_sumA = 0.0; g_sumB = 0.0; g_done = 0u;
    }
}

// Kernel 2: one CTA per row n, 11 warps (one per candidate k).
// Cache policy: Candidate is streamed (evict-first), outputs stream out,
// dtrain uses default caching so the 102 MB table stays L2-resident.
__global__ void __launch_bounds__(352) main_kernel(
    const float* __restrict__ Cand,     // [NO, KC, DIM]
    const float* __restrict__ ndist,    // [NO, KC]
    const int*   __restrict__ nind,     // [NO, KC]
    const float* __restrict__ dtrain,   // [NT, DIM]
    float*       __restrict__ out)
{
    __shared__ __align__(16) float sC[KC][DIM];  // candidate tile (11.25 KB)
    __shared__ __align__(16) float s_wa[2 * DIM];
    __shared__ float sScore[KC];
    __shared__ float sRow[KC];

    const int n    = blockIdx.x;
    const int tid  = threadIdx.x;
    const int w    = tid >> 5;    // 0..10 candidate index
    const int lane = tid & 31;

    // stage wa2 into smem
    for (int i = tid; i < 2 * DIM; i += 352) s_wa[i] = g_wa2[i];

    // early global loads (MLP): lane covers dims [lane*4, ...) and [128+lane*4, ...)
    const float4* cp = (const float4*)(Cand + ((size_t)n * KC + w) * DIM);
    float4 c0 = __ldcs(cp + lane);        // streaming: don't pollute L2
    float4 c1 = __ldcs(cp + lane + 32);
    const int ind = __ldcs(nind + n * KC + w);
    const float4* dp = (const float4*)(dtrain + (size_t)ind * DIM);
    float4 d0 = __ldg(dp + lane);         // caching: keep table in L2
    float4 d1 = __ldg(dp + lane + 32);

    __syncthreads();

    const float4* w4 = (const float4*)s_wa;
    float4 wl0 = w4[lane],      wl1 = w4[lane + 32];   // wa2[0:256]
    float4 wh0 = w4[lane + 64], wh1 = w4[lane + 96];   // wa2[256:512]

    float sc = c0.x*wl0.x + c0.y*wl0.y + c0.z*wl0.z + c0.w*wl0.w
             + c1.x*wl1.x + c1.y*wl1.y + c1.z*wl1.z + c1.w*wl1.w
             + d0.x*wh0.x + d0.y*wh0.y + d0.z*wh0.z + d0.w*wh0.w
             + d1.x*wh1.x + d1.y*wh1.y + d1.z*wh1.z + d1.w*wh1.w;
    float rs = d0.x + d0.y + d0.z + d0.w + d1.x + d1.y + d1.z + d1.w;

#pragma unroll
    for (int off = 16; off; off >>= 1) {
        sc += __shfl_down_sync(0xffffffffu, sc, off);
        rs += __shfl_down_sync(0xffffffffu, rs, off);
    }

    // stage candidate row in smem for the output copy
    ((float4*)sC[w])[lane]      = c0;
    ((float4*)sC[w])[lane + 32] = c1;
    if (lane == 0) { sScore[w] = sc; sRow[w] = rs; }
    __syncthreads();

    // dropped index = argmin of score; tie -> larger index (top_k keeps lower indices)
    float minv = sScore[0];
    int   drop = 0;
#pragma unroll
    for (int kk = 1; kk < KC; ++kk) {
        float v = sScore[kk];
        if (v <= minv) { minv = v; drop = kk; }
    }

    if (w < KSEL) {
        // Cand_sel[n, w, :] = Candidate[n, src, :]
        const int src = w + (w >= drop ? 1 : 0);
        float4* op = (float4*)(out + ((size_t)n * KSEL + w) * DIM);
        __stcs(op + lane,      ((const float4*)sC[src])[lane]);
        __stcs(op + lane + 32, ((const float4*)sC[src])[lane + 32]);
    } else {
        if (lane < KSEL) {
            const int src = lane + (lane >= drop ? 1 : 0);
            const size_t ND_OFF = (size_t)NO * KSEL * DIM;
            const size_t NI_OFF = ND_OFF + (size_t)NO * KSEL;
            __stcs(out + ND_OFF + (size_t)n * KSEL + lane, __ldcs(ndist + n * KC + src));
            __stcs(out + NI_OFF + (size_t)n * KSEL + lane, (float)__ldcs(nind + n * KC + src));
        } else if (lane == KSEL) {
            float sa = 0.f;
#pragma unroll
            for (int kk = 0; kk < KC; ++kk) if (kk != drop) sa += sRow[kk];
            atomicAdd(&g_sumA, (double)sa);
            atomicAdd(&g_sumB, (double)sRow[drop]);
            __threadfence();
            // last CTA to finish writes the two scalar outputs
            unsigned int prev = atomicAdd(&g_done, 1u);
            if (prev == NO - 1) {
                const size_t A_OFF = (size_t)NO * KSEL * DIM + 2ull * NO * KSEL;
                out[A_OFF]     = (float)(g_sumA / ((double)NO * KSEL));
                out[A_OFF + 1] = (float)(g_sumB / (double)NO);
            }
        }
    }
}

extern "C" void kernel_launch(void* const* d_in, const int* in_sizes, int n_in,
                              void* d_out, int out_size) {
    (void)out_size;
    // Identify inputs by element count (robust to presence/absence of the scalar `test`):
    //   Candidate    = 20000*11*256 = 56,320,000
    //   data_m_train = 100000*256   = 25,600,000
    //   neigh_dist / neigh_ind      =    220,000 (dist first in metadata order)
    //   W            = 512*128      =     65,536
    //   A            = 256
    const float* Cand   = nullptr;
    const float* ndist  = nullptr;
    const int*   nind   = nullptr;
    const float* dtrain = nullptr;
    const float* W      = nullptr;
    const float* A      = nullptr;
    for (int i = 0; i < n_in; ++i) {
        const int s = in_sizes[i];
        if      (s == 56320000) Cand   = (const float*)d_in[i];
        else if (s == 25600000) dtrain = (const float*)d_in[i];
        else if (s == 220000) {
            if (!ndist) ndist = (const float*)d_in[i];
            else        nind  = (const int*)d_in[i];
        }
        else if (s == 65536)    W      = (const float*)d_in[i];
        else if (s == 256)      A      = (const float*)d_in[i];
    }

    float* out = (float*)d_out;
    prep_kernel<<<64, 256>>>(W, A);        // 512 warps: one per wa2 element
    main_kernel<<<NO, 352>>>(Cand, ndist, nind, dtrain, out);
}

// round 4
// speedup vs baseline: 1.0302x; 1.0302x over previous
#include <cuda_runtime.h>

#define NO   20000
#define KC   11
#define DIM  256
#define OUTF 128
#define KSEL 10
#define NT   100000

// ---- scratch (no allocations allowed) ----
__device__ __align__(16) float g_wa2[2 * DIM];  // W @ A[OUTF:, 0], length 512
__device__ float        g_rowdot[NT];   // dtrain[t] . wa2[256:512]
__device__ float        g_rowsum[NT];   // sum(dtrain[t])
__device__ double       g_sumA;
__device__ double       g_sumB;
__device__ unsigned int g_done;

// Kernel 1: wa2[d] = sum_f W[d,f] * A[OUTF+f]; one warp per d (512 warps).
__global__ void __launch_bounds__(256) prep_kernel(const float* __restrict__ W,
                                                   const float* __restrict__ A) {
    const int warp = (blockIdx.x * blockDim.x + threadIdx.x) >> 5;  // 0..511 = d
    const int lane = threadIdx.x & 31;

    const float* wrow = W + (size_t)warp * OUTF;
    const float* a2   = A + OUTF;
    float acc = wrow[lane]      * a2[lane]
              + wrow[lane + 32] * a2[lane + 32]
              + wrow[lane + 64] * a2[lane + 64]
              + wrow[lane + 96] * a2[lane + 96];
#pragma unroll
    for (int off = 16; off; off >>= 1)
        acc += __shfl_down_sync(0xffffffffu, acc, off);
    if (lane == 0) g_wa2[warp] = acc;

    if (blockIdx.x == 0 && threadIdx.x == 0) {
        g_sumA = 0.0; g_sumB = 0.0; g_done = 0u;
    }
}

// Kernel 2: sequential full-BW scan of the train table.
// One warp per row: rowdot[t] = dtrain[t] . wa2_hi, rowsum[t] = sum(dtrain[t]).
__global__ void __launch_bounds__(256) scan_kernel(const float* __restrict__ dtrain) {
    const int row  = (blockIdx.x * blockDim.x + threadIdx.x) >> 5;
    const int lane = threadIdx.x & 31;
    if (row >= NT) return;

    const float4* dp = (const float4*)(dtrain + (size_t)row * DIM);
    float4 a = dp[lane];
    float4 b = dp[lane + 32];

    const float4* w4 = (const float4*)g_wa2;           // wa2_hi starts at index 64
    float4 wh0 = w4[lane + 64];
    float4 wh1 = w4[lane + 96];

    float dot = a.x*wh0.x + a.y*wh0.y + a.z*wh0.z + a.w*wh0.w
              + b.x*wh1.x + b.y*wh1.y + b.z*wh1.z + b.w*wh1.w;
    float sum = a.x + a.y + a.z + a.w + b.x + b.y + b.z + b.w;

#pragma unroll
    for (int off = 16; off; off >>= 1) {
        dot += __shfl_down_sync(0xffffffffu, dot, off);
        sum += __shfl_down_sync(0xffffffffu, sum, off);
    }
    if (lane == 0) { g_rowdot[row] = dot; g_rowsum[row] = sum; }
}

// Kernel 3: one CTA per row n, 11 warps (one per candidate k).
// No bulk gather: per-(n,k) table contribution is two scalar lookups.
__global__ void __launch_bounds__(352) main_kernel(
    const float* __restrict__ Cand,     // [NO, KC, DIM]
    const float* __restrict__ ndist,    // [NO, KC]
    const int*   __restrict__ nind,     // [NO, KC]
    float*       __restrict__ out)
{
    __shared__ __align__(16) float sC[KC][DIM];  // candidate tile (11.25 KB)
    __shared__ __align__(16) float s_wa[DIM];    // wa2_lo only
    __shared__ float sScore[KC];
    __shared__ float sRow[KC];

    const int n    = blockIdx.x;
    const int tid  = threadIdx.x;
    const int w    = tid >> 5;    // 0..10 candidate index
    const int lane = tid & 31;

    // lane 0 of each warp resolves the two table scalars (tiny, L2-resident)
    float rdot = 0.f, rsum = 0.f;
    if (lane == 0) {
        const int ind = nind[n * KC + w];
        rdot = g_rowdot[ind];
        rsum = g_rowsum[ind];
    }

    // stage wa2_lo into smem
    for (int i = tid; i < DIM; i += 352) s_wa[i] = g_wa2[i];

    // candidate row loads (coalesced, streaming)
    const float4* cp = (const float4*)(Cand + ((size_t)n * KC + w) * DIM);
    float4 c0 = cp[lane];
    float4 c1 = cp[lane + 32];

    __syncthreads();

    const float4* w4 = (const float4*)s_wa;
    float4 wl0 = w4[lane], wl1 = w4[lane + 32];

    float sc = c0.x*wl0.x + c0.y*wl0.y + c0.z*wl0.z + c0.w*wl0.w
             + c1.x*wl1.x + c1.y*wl1.y + c1.z*wl1.z + c1.w*wl1.w;

#pragma unroll
    for (int off = 16; off; off >>= 1)
        sc += __shfl_down_sync(0xffffffffu, sc, off);

    // stage candidate row in smem for the output copy
    ((float4*)sC[w])[lane]      = c0;
    ((float4*)sC[w])[lane + 32] = c1;
    if (lane == 0) { sScore[w] = sc + rdot; sRow[w] = rsum; }
    __syncthreads();

    // dropped index = argmin of score; tie -> larger index (top_k keeps lower indices)
    float minv = sScore[0];
    int   drop = 0;
#pragma unroll
    for (int kk = 1; kk < KC; ++kk) {
        float v = sScore[kk];
        if (v <= minv) { minv = v; drop = kk; }
    }

    if (w < KSEL) {
        // Cand_sel[n, w, :] = Candidate[n, src, :]
        const int src = w + (w >= drop ? 1 : 0);
        float4* op = (float4*)(out + ((size_t)n * KSEL + w) * DIM);
        op[lane]      = ((const float4*)sC[src])[lane];
        op[lane + 32] = ((const float4*)sC[src])[lane + 32];
    } else {
        if (lane < KSEL) {
            const int src = lane + (lane >= drop ? 1 : 0);
            const size_t ND_OFF = (size_t)NO * KSEL * DIM;
            const size_t NI_OFF = ND_OFF + (size_t)NO * KSEL;
            out[ND_OFF + (size_t)n * KSEL + lane] = ndist[n * KC + src];
            out[NI_OFF + (size_t)n * KSEL + lane] = (float)nind[n * KC + src];
        } else if (lane == KSEL) {
            float sa = 0.f;
#pragma unroll
            for (int kk = 0; kk < KC; ++kk) if (kk != drop) sa += sRow[kk];
            atomicAdd(&g_sumA, (double)sa);
            atomicAdd(&g_sumB, (double)sRow[drop]);
            __threadfence();
            unsigned int prev = atomicAdd(&g_done, 1u);
            if (prev == NO - 1) {
                const size_t A_OFF = (size_t)NO * KSEL * DIM + 2ull * NO * KSEL;
                out[A_OFF]     = (float)(g_sumA / ((double)NO * KSEL));
                out[A_OFF + 1] = (float)(g_sumB / (double)NO);
            }
        }
    }
}

extern "C" void kernel_launch(void* const* d_in, const int* in_sizes, int n_in,
                              void* d_out, int out_size) {
    (void)out_size;
    const float* Cand   = nullptr;
    const float* ndist  = nullptr;
    const int*   nind   = nullptr;
    const float* dtrain = nullptr;
    const float* W      = nullptr;
    const float* A      = nullptr;
    for (int i = 0; i < n_in; ++i) {
        const int s = in_sizes[i];
        if      (s == 56320000) Cand   = (const float*)d_in[i];
        else if (s == 25600000) dtrain = (const float*)d_in[i];
        else if (s == 220000) {
            if (!ndist) ndist = (const float*)d_in[i];
            else        nind  = (const int*)d_in[i];
        }
        else if (s == 65536)    W      = (const float*)d_in[i];
        else if (s == 256)      A      = (const float*)d_in[i];
    }

    float* out = (float*)d_out;
    prep_kernel<<<64, 256>>>(W, A);                 // wa2
    scan_kernel<<<(NT * 32 + 255) / 256, 256>>>(dtrain);  // rowdot/rowsum, streaming
    main_kernel<<<NO, 352>>>(Cand, ndist, nind, out);
}

// round 5
// speedup vs baseline: 1.1975x; 1.1623x over previous
#include <cuda_runtime.h>

#define NO   20000
#define KC   11
#define DIM  256
#define OUTF 128
#define KSEL 10
#define NT   100000

// ---- scratch (no allocations allowed) ----
__device__ __align__(16) float g_wa2[2 * DIM];  // W @ A[OUTF:, 0], length 512
__device__ float  g_rowdot[NT];   // dtrain[t] . wa2[256:512]
__device__ float  g_rowsum[NT];   // sum(dtrain[t])
__device__ double g_sumA;
__device__ double g_sumB;

// Kernel 1: wa2[d] = sum_f W[d,f] * A[OUTF+f]; one warp per d (512 warps).
__global__ void __launch_bounds__(256) prep_kernel(const float* __restrict__ W,
                                                   const float* __restrict__ A) {
    const int warp = (blockIdx.x * blockDim.x + threadIdx.x) >> 5;  // 0..511 = d
    const int lane = threadIdx.x & 31;

    const float* wrow = W + (size_t)warp * OUTF;
    const float* a2   = A + OUTF;
    float acc = wrow[lane]      * a2[lane]
              + wrow[lane + 32] * a2[lane + 32]
              + wrow[lane + 64] * a2[lane + 64]
              + wrow[lane + 96] * a2[lane + 96];
#pragma unroll
    for (int off = 16; off; off >>= 1)
        acc += __shfl_down_sync(0xffffffffu, acc, off);
    if (lane == 0) g_wa2[warp] = acc;

    if (blockIdx.x == 0 && threadIdx.x == 0) { g_sumA = 0.0; g_sumB = 0.0; }
}

// Kernel 2: sequential full-BW scan of the train table.
// One warp per row: rowdot[t] = dtrain[t] . wa2_hi, rowsum[t] = sum(dtrain[t]).
__global__ void __launch_bounds__(256) scan_kernel(const float* __restrict__ dtrain) {
    const int row  = (blockIdx.x * blockDim.x + threadIdx.x) >> 5;
    const int lane = threadIdx.x & 31;
    if (row >= NT) return;

    const float4* dp = (const float4*)(dtrain + (size_t)row * DIM);
    float4 a = dp[lane];
    float4 b = dp[lane + 32];

    const float4* w4 = (const float4*)g_wa2;           // wa2_hi starts at float4 index 64
    float4 wh0 = w4[lane + 64];
    float4 wh1 = w4[lane + 96];

    float dot = a.x*wh0.x + a.y*wh0.y + a.z*wh0.z + a.w*wh0.w
              + b.x*wh1.x + b.y*wh1.y + b.z*wh1.z + b.w*wh1.w;
    float sum = a.x + a.y + a.z + a.w + b.x + b.y + b.z + b.w;

#pragma unroll
    for (int off = 16; off; off >>= 1) {
        dot += __shfl_down_sync(0xffffffffu, dot, off);
        sum += __shfl_down_sync(0xffffffffu, sum, off);
    }
    if (lane == 0) { g_rowdot[row] = dot; g_rowsum[row] = sum; }
}

// Kernel 3: one CTA per row n, 11 warps (one per candidate k). No fences.
__global__ void __launch_bounds__(352) main_kernel(
    const float* __restrict__ Cand,     // [NO, KC, DIM]
    const float* __restrict__ ndist,    // [NO, KC]
    const int*   __restrict__ nind,     // [NO, KC]
    float*       __restrict__ out)
{
    __shared__ __align__(16) float sC[KC][DIM];  // candidate tile (11.25 KB)
    __shared__ __align__(16) float s_wa[DIM];    // wa2_lo only
    __shared__ float sScore[KC];
    __shared__ float sRow[KC];

    const int n    = blockIdx.x;
    const int tid  = threadIdx.x;
    const int w    = tid >> 5;    // 0..10 candidate index
    const int lane = tid & 31;

    // lane 0 of each warp resolves the two table scalars (tiny, L2-resident)
    float rdot = 0.f, rsum = 0.f;
    if (lane == 0) {
        const int ind = nind[n * KC + w];
        rdot = g_rowdot[ind];
        rsum = g_rowsum[ind];
    }

    // stage wa2_lo into smem
    for (int i = tid; i < DIM; i += 352) s_wa[i] = g_wa2[i];

    // candidate row loads (coalesced)
    const float4* cp = (const float4*)(Cand + ((size_t)n * KC + w) * DIM);
    float4 c0 = cp[lane];
    float4 c1 = cp[lane + 32];

    __syncthreads();

    const float4* w4 = (const float4*)s_wa;
    float4 wl0 = w4[lane], wl1 = w4[lane + 32];

    float sc = c0.x*wl0.x + c0.y*wl0.y + c0.z*wl0.z + c0.w*wl0.w
             + c1.x*wl1.x + c1.y*wl1.y + c1.z*wl1.z + c1.w*wl1.w;

#pragma unroll
    for (int off = 16; off; off >>= 1)
        sc += __shfl_down_sync(0xffffffffu, sc, off);

    // stage candidate row in smem for the output copy
    ((float4*)sC[w])[lane]      = c0;
    ((float4*)sC[w])[lane + 32] = c1;
    if (lane == 0) { sScore[w] = sc + rdot; sRow[w] = rsum; }
    __syncthreads();

    // dropped index = argmin of score; tie -> larger index (top_k keeps lower indices)
    float minv = sScore[0];
    int   drop = 0;
#pragma unroll
    for (int kk = 1; kk < KC; ++kk) {
        float v = sScore[kk];
        if (v <= minv) { minv = v; drop = kk; }
    }

    if (w < KSEL) {
        // Cand_sel[n, w, :] = Candidate[n, src, :]
        const int src = w + (w >= drop ? 1 : 0);
        float4* op = (float4*)(out + ((size_t)n * KSEL + w) * DIM);
        op[lane]      = ((const float4*)sC[src])[lane];
        op[lane + 32] = ((const float4*)sC[src])[lane + 32];
    } else {
        if (lane < KSEL) {
            const int src = lane + (lane >= drop ? 1 : 0);
            const size_t ND_OFF = (size_t)NO * KSEL * DIM;
            const size_t NI_OFF = ND_OFF + (size_t)NO * KSEL;
            out[ND_OFF + (size_t)n * KSEL + lane] = ndist[n * KC + src];
            out[NI_OFF + (size_t)n * KSEL + lane] = (float)nind[n * KC + src];
        } else if (lane == KSEL) {
            float sa = 0.f;
#pragma unroll
            for (int kk = 0; kk < KC; ++kk) if (kk != drop) sa += sRow[kk];
            atomicAdd(&g_sumA, (double)sa);
            atomicAdd(&g_sumB, (double)sRow[drop]);
        }
    }
}

// Kernel 4: write the two scalars
__global__ void finish_kernel(float* __restrict__ out) {
    const size_t A_OFF = (size_t)NO * KSEL * DIM + 2ull * NO * KSEL;
    out[A_OFF]     = (float)(g_sumA / ((double)NO * KSEL));
    out[A_OFF + 1] = (float)(g_sumB / (double)NO);
}

extern "C" void kernel_launch(void* const* d_in, const int* in_sizes, int n_in,
                              void* d_out, int out_size) {
    (void)out_size;
    const float* Cand   = nullptr;
    const float* ndist  = nullptr;
    const int*   nind   = nullptr;
    const float* dtrain = nullptr;
    const float* W      = nullptr;
    const float* A      = nullptr;
    for (int i = 0; i < n_in; ++i) {
        const int s = in_sizes[i];
        if      (s == 56320000) Cand   = (const float*)d_in[i];
        else if (s == 25600000) dtrain = (const float*)d_in[i];
        else if (s == 220000) {
            if (!ndist) ndist = (const float*)d_in[i];
            else        nind  = (const int*)d_in[i];
        }
        else if (s == 65536)    W      = (const float*)d_in[i];
        else if (s == 256)      A      = (const float*)d_in[i];
    }

    float* out = (float*)d_out;
    prep_kernel<<<64, 256>>>(W, A);                       // wa2 + zero sums
    scan_kernel<<<(NT * 32 + 255) / 256, 256>>>(dtrain);  // rowdot/rowsum, streaming
    main_kernel<<<NO, 352>>>(Cand, ndist, nind, out);
    finish_kernel<<<1, 1>>>(out);
}

// round 6
// speedup vs baseline: 1.2777x; 1.0670x over previous
#include <cuda_runtime.h>

#define NO    20000
#define KC    11
#define DIM   256
#define OUTF  128
#define KSEL  10
#define NT    100000
#define ROWS  4                 // rows of n per main CTA

// ---- scratch (no allocations allowed) ----
__device__ __align__(16) float g_wa2[2 * DIM];  // W @ A[OUTF:, 0], length 512
__device__ float  g_rowdot[NT];   // dtrain[t] . wa2[256:512]
__device__ float  g_rowsum[NT];   // sum(dtrain[t])
__device__ double g_sumA;
__device__ double g_sumB;

// Kernel 1: wa2[d] = sum_f W[d,f] * A[OUTF+f]; one warp per d (512 warps).
__global__ void __launch_bounds__(256) prep_kernel(const float* __restrict__ W,
                                                   const float* __restrict__ A) {
    const int warp = (blockIdx.x * blockDim.x + threadIdx.x) >> 5;  // 0..511 = d
    const int lane = threadIdx.x & 31;

    const float* wrow = W + (size_t)warp * OUTF;
    const float* a2   = A + OUTF;
    float acc = wrow[lane]      * a2[lane]
              + wrow[lane + 32] * a2[lane + 32]
              + wrow[lane + 64] * a2[lane + 64]
              + wrow[lane + 96] * a2[lane + 96];
#pragma unroll
    for (int off = 16; off; off >>= 1)
        acc += __shfl_down_sync(0xffffffffu, acc, off);
    if (lane == 0) g_wa2[warp] = acc;
    if (blockIdx.x == 0 && threadIdx.x == 0) { g_sumA = 0.0; g_sumB = 0.0; }

    cudaTriggerProgrammaticLaunchCompletion();
}

// Kernel 2: streaming scan of the train table; one warp per row.
// PDL: dtrain loads are issued before waiting for prep's g_wa2.
__global__ void __launch_bounds__(256) scan_kernel(const float* __restrict__ dtrain) {
    const int row  = (blockIdx.x * blockDim.x + threadIdx.x) >> 5;
    const int lane = threadIdx.x & 31;

    float4 a = {0,0,0,0}, b = {0,0,0,0};
    if (row < NT) {
        const float4* dp = (const float4*)(dtrain + (size_t)row * DIM);
        a = dp[lane];
        b = dp[lane + 32];
    }

    cudaGridDependencySynchronize();   // wait for prep (g_wa2)

    const float4* w4 = (const float4*)g_wa2;   // wa2_hi at float4 index 64
    float4 wh0 = w4[lane + 64];
    float4 wh1 = w4[lane + 96];

    float dot = a.x*wh0.x + a.y*wh0.y + a.z*wh0.z + a.w*wh0.w
              + b.x*wh1.x + b.y*wh1.y + b.z*wh1.z + b.w*wh1.w;
    float sum = a.x + a.y + a.z + a.w + b.x + b.y + b.z + b.w;

#pragma unroll
    for (int off = 16; off; off >>= 1) {
        dot += __shfl_down_sync(0xffffffffu, dot, off);
        sum += __shfl_down_sync(0xffffffffu, sum, off);
    }
    if (row < NT && lane == 0) { g_rowdot[row] = dot; g_rowsum[row] = sum; }

    cudaTriggerProgrammaticLaunchCompletion();
}

// Kernel 3: ROWS rows of n per CTA, 11 warps (one per candidate k).
// PDL: first row's Candidate loads issued before waiting on scan.
__global__ void __launch_bounds__(352) main_kernel(
    const float* __restrict__ Cand,     // [NO, KC, DIM]
    const float* __restrict__ ndist,    // [NO, KC]
    const int*   __restrict__ nind,     // [NO, KC]
    float*       __restrict__ out)
{
    __shared__ __align__(16) float sC[KC][DIM];
    __shared__ __align__(16) float s_wa[DIM];
    __shared__ float sScore[KC];
    __shared__ float sRow[KC];

    const int base = blockIdx.x * ROWS;
    const int tid  = threadIdx.x;
    const int w    = tid >> 5;    // 0..10 candidate index
    const int lane = tid & 31;

    // issue first row's candidate loads (independent of scan output)
    const float4* cp = (const float4*)(Cand + ((size_t)base * KC + w) * DIM);
    float4 c0 = cp[lane];
    float4 c1 = cp[lane + 32];

    cudaGridDependencySynchronize();   // wait for scan (g_rowdot/g_rowsum; g_wa2 transitively)

    for (int i = tid; i < DIM; i += 352) s_wa[i] = g_wa2[i];

    const size_t ND_OFF = (size_t)NO * KSEL * DIM;
    const size_t NI_OFF = ND_OFF + (size_t)NO * KSEL;

#pragma unroll
    for (int r = 0; r < ROWS; ++r) {
        const int n = base + r;

        // per-candidate table scalars (tiny, L2-resident)
        float rdot = 0.f, rsum = 0.f;
        if (lane == 0) {
            const int ind = nind[n * KC + w];
            rdot = g_rowdot[ind];
            rsum = g_rowsum[ind];
        }

        __syncthreads();   // s_wa ready (iter 0); sC consumed (iter >0)

        const float4* w4 = (const float4*)s_wa;
        float4 wl0 = w4[lane], wl1 = w4[lane + 32];

        float sc = c0.x*wl0.x + c0.y*wl0.y + c0.z*wl0.z + c0.w*wl0.w
                 + c1.x*wl1.x + c1.y*wl1.y + c1.z*wl1.z + c1.w*wl1.w;
#pragma unroll
        for (int off = 16; off; off >>= 1)
            sc += __shfl_down_sync(0xffffffffu, sc, off);

        ((float4*)sC[w])[lane]      = c0;
        ((float4*)sC[w])[lane + 32] = c1;
        if (lane == 0) { sScore[w] = sc + rdot; sRow[w] = rsum; }

        // prefetch next row's candidate (overlaps barrier + copy-out)
        if (r + 1 < ROWS) {
            const float4* cpn = (const float4*)(Cand + ((size_t)(n + 1) * KC + w) * DIM);
            c0 = cpn[lane];
            c1 = cpn[lane + 32];
        }

        __syncthreads();

        // dropped index = argmin; tie -> larger index (top_k keeps lower indices)
        float minv = sScore[0];
        int   drop = 0;
#pragma unroll
        for (int kk = 1; kk < KC; ++kk) {
            float v = sScore[kk];
            if (v <= minv) { minv = v; drop = kk; }
        }

        if (w < KSEL) {
            const int src = w + (w >= drop ? 1 : 0);
            float4* op = (float4*)(out + ((size_t)n * KSEL + w) * DIM);
            op[lane]      = ((const float4*)sC[src])[lane];
            op[lane + 32] = ((const float4*)sC[src])[lane + 32];
        } else {
            if (lane < KSEL) {
                const int src = lane + (lane >= drop ? 1 : 0);
                out[ND_OFF + (size_t)n * KSEL + lane] = ndist[n * KC + src];
                out[NI_OFF + (size_t)n * KSEL + lane] = (float)nind[n * KC + src];
            } else if (lane == KSEL) {
                float sa = 0.f;
#pragma unroll
                for (int kk = 0; kk < KC; ++kk) if (kk != drop) sa += sRow[kk];
                atomicAdd(&g_sumA, (double)sa);
                atomicAdd(&g_sumB, (double)sRow[drop]);
            }
        }
    }
    cudaTriggerProgrammaticLaunchCompletion();
}

// Kernel 4: write the two scalars
__global__ void finish_kernel(float* __restrict__ out) {
    cudaGridDependencySynchronize();
    const size_t A_OFF = (size_t)NO * KSEL * DIM + 2ull * NO * KSEL;
    out[A_OFF]     = (float)(g_sumA / ((double)NO * KSEL));
    out[A_OFF + 1] = (float)(g_sumB / (double)NO);
}

static inline void launch_pdl(void* func, dim3 grid, dim3 block, void** args) {
    cudaLaunchConfig_t cfg = {};
    cudaLaunchAttribute attr[1];
    attr[0].id = cudaLaunchAttributeProgrammaticStreamSerialization;
    attr[0].val.programmaticStreamSerializationAllowed = 1;
    cfg.gridDim = grid; cfg.blockDim = block;
    cfg.stream = 0; cfg.attrs = attr; cfg.numAttrs = 1;
    cudaLaunchKernelExC(&cfg, func, args);
}

extern "C" void kernel_launch(void* const* d_in, const int* in_sizes, int n_in,
                              void* d_out, int out_size) {
    (void)out_size;
    const float* Cand   = nullptr;
    const float* ndist  = nullptr;
    const int*   nind   = nullptr;
    const float* dtrain = nullptr;
    const float* W      = nullptr;
    const float* A      = nullptr;
    for (int i = 0; i < n_in; ++i) {
        const int s = in_sizes[i];
        if      (s == 56320000) Cand   = (const float*)d_in[i];
        else if (s == 25600000) dtrain = (const float*)d_in[i];
        else if (s == 220000) {
            if (!ndist) ndist = (const float*)d_in[i];
            else        nind  = (const int*)d_in[i];
        }
        else if (s == 65536)    W      = (const float*)d_in[i];
        else if (s == 256)      A      = (const float*)d_in[i];
    }

    float* out = (float*)d_out;

    prep_kernel<<<64, 256>>>(W, A);

    {   // scan (PDL after prep)
        void* args[] = { (void*)&dtrain };
        launch_pdl((void*)scan_kernel, dim3((NT * 32 + 255) / 256), dim3(256), args);
    }
    {   // main (PDL after scan)
        void* args[] = { (void*)&Cand, (void*)&ndist, (void*)&nind, (void*)&out };
        launch_pdl((void*)main_kernel, dim3(NO / ROWS), dim3(352), args);
    }
    {   // finish (PDL after main)
        void* args[] = { (void*)&out };
        launch_pdl((void*)finish_kernel, dim3(1), dim3(1), args);
    }
}